// round 1
// baseline (speedup 1.0000x reference)
#include <cuda_runtime.h>
#include <math.h>

#define KTOK 16384
#define DMOD 1024

// Scratch (static __device__ arrays per allocation rules)
__device__ float g_H[(size_t)KTOK * 512];       // relu(pos@W1+b1)
__device__ float g_jk[(size_t)KTOK * 1024];     // joint_mlp output
__device__ float g_comb[(size_t)KTOK * 4096];   // [jk | gamma_k | jk[parent] | gamma_pk]
__device__ float g_h3[(size_t)KTOK * 2048];     // relu(comb@W3+b3)

// ---------------------------------------------------------------------------
// Stage 1: H[r][j] = relu(b1[j] + sum_c pos[r][c] * W1[c][j]),  j in [0,512)
// ---------------------------------------------------------------------------
__global__ void mlp1_kernel(const float* __restrict__ pos,
                            const float* __restrict__ W1,
                            const float* __restrict__ b1) {
    int idx = blockIdx.x * blockDim.x + threadIdx.x;   // K*512 threads
    int r = idx >> 9;
    int j = idx & 511;
    float p0 = pos[r * 3 + 0];
    float p1 = pos[r * 3 + 1];
    float p2 = pos[r * 3 + 2];
    float a = b1[j];
    a = fmaf(p0, W1[j], a);
    a = fmaf(p1, W1[512 + j], a);
    a = fmaf(p2, W1[1024 + j], a);
    g_H[idx] = fmaxf(a, 0.0f);
}

// ---------------------------------------------------------------------------
// Stage 3: build combined row r:
//   [0:1024)    jk[r]
//   [1024:2048) sinusoidal(r)
//   [2048:3072) jk[parent[r]]
//   [3072:4096) sinusoidal(parent[r])
// One thread per (r, i) pair, i in [0,512): handles 2 jk floats x2 + sin/cos x2
// ---------------------------------------------------------------------------
__global__ void build_combined_kernel(const int* __restrict__ parent) {
    int idx = blockIdx.x * blockDim.x + threadIdx.x;   // K*512 threads
    int r = idx >> 9;
    int i = idx & 511;
    int p = parent[r];

    const float2* jkr = (const float2*)(g_jk + (size_t)r * 1024);
    const float2* jkp = (const float2*)(g_jk + (size_t)p * 1024);
    float2 a = jkr[i];
    float2 b = jkp[i];

    float denom = powf(10000.0f, (2.0f * (float)i) * (1.0f / 1024.0f));
    float inv = 1.0f / denom;
    float sr, cr, sp, cp;
    __sincosf(0.0f, &sr, &cr); // dummy to keep compiler honest? (removed below)
    sincosf((float)r / denom, &sr, &cr);
    sincosf((float)p / denom, &sp, &cp);
    (void)inv;

    float2* row = (float2*)(g_comb + (size_t)r * 4096);
    row[i]        = a;
    row[512 + i]  = make_float2(sr, cr);
    row[1024 + i] = b;
    row[1536 + i] = make_float2(sp, cp);
}

// ---------------------------------------------------------------------------
// Register-tiled SGEMM: C[M,N] = opt_relu(A[M,Kd] @ B[Kd,N] + bias[N])
// BM=BN=128, BK=8, 256 threads, 8x8 per thread. All dims divisible (checked):
// M=16384, N in {1024,2048}, Kd in {512,4096,2048}.
// ---------------------------------------------------------------------------
template <bool RELU>
__global__ __launch_bounds__(256, 2) void sgemm_kernel(
    const float* __restrict__ A, const float* __restrict__ B,
    const float* __restrict__ bias, float* __restrict__ C,
    int M, int N, int Kd) {
    const int BM = 128, BN = 128, BK = 8, TM = 8, TN = 8;
    __shared__ float As[BK][BM];
    __shared__ float Bs[BK][BN];

    int tid = threadIdx.x;
    int br = blockIdx.y;   // M tile
    int bc = blockIdx.x;   // N tile

    const float* Ab = A + (size_t)br * BM * Kd;
    const float* Bb = B + (size_t)bc * BN;

    // A-tile loader: 128 rows x 8 cols, one float4 along K per thread
    int aRow = tid >> 1;
    int aCol = (tid & 1) * 4;
    // B-tile loader: 8 rows x 128 cols, one float4 along N per thread
    int bRow = tid >> 5;
    int bCol = (tid & 31) * 4;
    // Compute-tile coords: 16x16 threads, each 8x8
    int tRow = (tid >> 4) * TM;
    int tCol = (tid & 15) * TN;

    float acc[TM][TN];
#pragma unroll
    for (int i = 0; i < TM; i++)
#pragma unroll
        for (int j = 0; j < TN; j++) acc[i][j] = 0.0f;

    float regM[TM], regN[TN];

    for (int k0 = 0; k0 < Kd; k0 += BK) {
        float4 av = *(const float4*)(Ab + (size_t)aRow * Kd + k0 + aCol);
        As[aCol + 0][aRow] = av.x;
        As[aCol + 1][aRow] = av.y;
        As[aCol + 2][aRow] = av.z;
        As[aCol + 3][aRow] = av.w;
        float4 bv = *(const float4*)(Bb + (size_t)(k0 + bRow) * N + bCol);
        *(float4*)&Bs[bRow][bCol] = bv;
        __syncthreads();

#pragma unroll
        for (int kk = 0; kk < BK; kk++) {
#pragma unroll
            for (int i = 0; i < TM; i += 4)
                *(float4*)&regM[i] = *(const float4*)&As[kk][tRow + i];
#pragma unroll
            for (int j = 0; j < TN; j += 4)
                *(float4*)&regN[j] = *(const float4*)&Bs[kk][tCol + j];
#pragma unroll
            for (int i = 0; i < TM; i++)
#pragma unroll
                for (int j = 0; j < TN; j++)
                    acc[i][j] = fmaf(regM[i], regN[j], acc[i][j]);
        }
        __syncthreads();
    }

    // Epilogue: bias + optional relu, float4 stores
    float bvreg[TN];
#pragma unroll
    for (int j = 0; j < TN; j++) bvreg[j] = bias[(size_t)bc * BN + tCol + j];

#pragma unroll
    for (int i = 0; i < TM; i++) {
        float* Crow = C + (size_t)(br * BM + tRow + i) * N + (size_t)bc * BN + tCol;
#pragma unroll
        for (int j = 0; j < TN; j += 4) {
            float4 v;
            v.x = acc[i][j + 0] + bvreg[j + 0];
            v.y = acc[i][j + 1] + bvreg[j + 1];
            v.z = acc[i][j + 2] + bvreg[j + 2];
            v.w = acc[i][j + 3] + bvreg[j + 3];
            if (RELU) {
                v.x = fmaxf(v.x, 0.0f);
                v.y = fmaxf(v.y, 0.0f);
                v.z = fmaxf(v.z, 0.0f);
                v.w = fmaxf(v.w, 0.0f);
            }
            *(float4*)(Crow + j) = v;
        }
    }
}

// ---------------------------------------------------------------------------
// Launch
// Inputs (metadata order): positions, parent_indices, W1, b1, W2, b2,
//                          W3, b3, W4, b4
// ---------------------------------------------------------------------------
extern "C" void kernel_launch(void* const* d_in, const int* in_sizes, int n_in,
                              void* d_out, int out_size) {
    const float* positions = (const float*)d_in[0];
    const int*   parent    = (const int*)d_in[1];
    const float* W1 = (const float*)d_in[2];
    const float* b1 = (const float*)d_in[3];
    const float* W2 = (const float*)d_in[4];
    const float* b2 = (const float*)d_in[5];
    const float* W3 = (const float*)d_in[6];
    const float* b3 = (const float*)d_in[7];
    const float* W4 = (const float*)d_in[8];
    const float* b4 = (const float*)d_in[9];
    float* out = (float*)d_out;

    float* dH;    cudaGetSymbolAddress((void**)&dH,   g_H);
    float* djk;   cudaGetSymbolAddress((void**)&djk,  g_jk);
    float* dcomb; cudaGetSymbolAddress((void**)&dcomb, g_comb);
    float* dh3;   cudaGetSymbolAddress((void**)&dh3,  g_h3);

    // Stage 1: H = relu(pos @ W1 + b1)   [K,512]
    mlp1_kernel<<<(KTOK * 512) / 256, 256>>>(positions, W1, b1);

    // Stage 2: jk = H @ W2 + b2          [K,1024]
    {
        dim3 grid(1024 / 128, KTOK / 128);
        sgemm_kernel<false><<<grid, 256>>>(dH, W2, b2, djk, KTOK, 1024, 512);
    }

    // Stage 3: combined                  [K,4096]
    build_combined_kernel<<<(KTOK * 512) / 256, 256>>>(parent);

    // Stage 4: h = relu(combined @ W3 + b3)   [K,2048]
    {
        dim3 grid(2048 / 128, KTOK / 128);
        sgemm_kernel<true><<<grid, 256>>>(dcomb, W3, b3, dh3, KTOK, 2048, 4096);
    }

    // Stage 5: out = h @ W4 + b4         [K,1024]
    {
        dim3 grid(1024 / 128, KTOK / 128);
        sgemm_kernel<false><<<grid, 256>>>(dh3, W4, b4, out, KTOK, 1024, 2048);
    }
}

// round 3
// speedup vs baseline: 2.6537x; 2.6537x over previous
#include <cuda_runtime.h>
#include <cuda_fp16.h>
#include <math.h>
#include <stdint.h>

#define KTOK 16384
#define DMOD 1024

// ---------------------------------------------------------------------------
// Scratch (__device__ globals per allocation rules)
// ---------------------------------------------------------------------------
__device__ __half g_Hh[(size_t)KTOK * 512];
__device__ __half g_Hl[(size_t)KTOK * 512];
__device__ float  g_jk[(size_t)KTOK * 1024];
__device__ __half g_combh[(size_t)KTOK * 4096];
__device__ __half g_combl[(size_t)KTOK * 4096];
__device__ __half g_h3h[(size_t)KTOK * 2048];
__device__ __half g_h3l[(size_t)KTOK * 2048];
// transposed + split weights: Wt[N][Kd] (K contiguous)
__device__ __half g_W2th[1024 * 512];
__device__ __half g_W2tl[1024 * 512];
__device__ __half g_W3th[(size_t)2048 * 4096];
__device__ __half g_W3tl[(size_t)2048 * 4096];
__device__ __half g_W4th[1024 * 2048];
__device__ __half g_W4tl[1024 * 2048];

// ---------------------------------------------------------------------------
// PTX primitives (all plain sm_80-era: compile under compute_103)
// ---------------------------------------------------------------------------
__device__ __forceinline__ uint32_t smem_u32(const void* p) {
    uint32_t a;
    asm("{ .reg .u64 t; cvta.to.shared.u64 t, %1; cvt.u32.u64 %0, t; }" : "=r"(a) : "l"(p));
    return a;
}
__device__ __forceinline__ void cp_async16(uint32_t dst, const void* src) {
    asm volatile("cp.async.cg.shared.global [%0], [%1], 16;" :: "r"(dst), "l"(src));
}
#define CP_COMMIT() asm volatile("cp.async.commit_group;" ::: "memory")
#define CP_WAIT(n)  asm volatile("cp.async.wait_group %0;" :: "n"(n) : "memory")

__device__ __forceinline__ void ldsm_x4(uint32_t* r, uint32_t addr) {
    asm volatile("ldmatrix.sync.aligned.m8n8.x4.shared.b16 {%0,%1,%2,%3}, [%4];"
                 : "=r"(r[0]), "=r"(r[1]), "=r"(r[2]), "=r"(r[3]) : "r"(addr));
}
__device__ __forceinline__ void mma16816(float* d, const uint32_t* a,
                                         uint32_t b0, uint32_t b1) {
    asm volatile("mma.sync.aligned.m16n8k16.row.col.f32.f16.f16.f32 "
                 "{%0,%1,%2,%3}, {%4,%5,%6,%7}, {%8,%9}, {%0,%1,%2,%3};"
                 : "+f"(d[0]), "+f"(d[1]), "+f"(d[2]), "+f"(d[3])
                 : "r"(a[0]), "r"(a[1]), "r"(a[2]), "r"(a[3]), "r"(b0), "r"(b1));
}

__device__ __forceinline__ void split_store(__half* hi, __half* lo, size_t idx, float v) {
    __half h = __float2half_rn(v);
    hi[idx] = h;
    lo[idx] = __float2half_rn(v - __half2float(h));
}

// ---------------------------------------------------------------------------
// Stage 1: H = relu(pos @ W1 + b1) -> hi/lo fp16  [K,512]
// ---------------------------------------------------------------------------
__global__ void mlp1_kernel(const float* __restrict__ pos,
                            const float* __restrict__ W1,
                            const float* __restrict__ b1) {
    int idx = blockIdx.x * blockDim.x + threadIdx.x;
    int r = idx >> 9;
    int j = idx & 511;
    float a = b1[j];
    a = fmaf(pos[r * 3 + 0], W1[j], a);
    a = fmaf(pos[r * 3 + 1], W1[512 + j], a);
    a = fmaf(pos[r * 3 + 2], W1[1024 + j], a);
    a = fmaxf(a, 0.0f);
    split_store(g_Hh, g_Hl, (size_t)idx, a);
}

// ---------------------------------------------------------------------------
// Transpose + split: in fp32 [R,C] -> out hi/lo fp16 [C,R]
// ---------------------------------------------------------------------------
__global__ void transpose_split_kernel(const float* __restrict__ in,
                                       __half* __restrict__ oh,
                                       __half* __restrict__ ol,
                                       int R, int C) {
    __shared__ float tile[32][33];
    int c = blockIdx.x * 32 + threadIdx.x;
    int r0 = blockIdx.y * 32;
#pragma unroll
    for (int k = 0; k < 32; k += 8)
        tile[threadIdx.y + k][threadIdx.x] = in[(size_t)(r0 + threadIdx.y + k) * C + c];
    __syncthreads();
    int orow0 = blockIdx.x * 32;
    int ocol = r0 + threadIdx.x;
#pragma unroll
    for (int k = 0; k < 32; k += 8) {
        float v = tile[threadIdx.x][threadIdx.y + k];
        split_store(oh, ol, (size_t)(orow0 + threadIdx.y + k) * R + ocol, v);
    }
}

// ---------------------------------------------------------------------------
// Stage 3: combined row r -> hi/lo fp16 [K,4096]
//   [0:1024) jk[r] | [1024:2048) gamma(r) | [2048:3072) jk[p] | [3072:4096) gamma(p)
// ---------------------------------------------------------------------------
__global__ void build_combined_kernel(const int* __restrict__ parent) {
    int idx = blockIdx.x * blockDim.x + threadIdx.x;   // K*512 threads
    int r = idx >> 9;
    int i = idx & 511;
    int p = parent[r];

    const float2* jkr = (const float2*)(g_jk + (size_t)r * 1024);
    const float2* jkp = (const float2*)(g_jk + (size_t)p * 1024);
    float2 a = jkr[i];
    float2 b = jkp[i];

    float denom = powf(10000.0f, (2.0f * (float)i) * (1.0f / 1024.0f));
    float sr, cr, sp, cp;
    sincosf((float)r / denom, &sr, &cr);
    sincosf((float)p / denom, &sp, &cp);

    size_t base = (size_t)r * 4096;
    int c2 = 2 * i;
    split_store(g_combh, g_combl, base + c2, a.x);
    split_store(g_combh, g_combl, base + c2 + 1, a.y);
    split_store(g_combh, g_combl, base + 1024 + c2, sr);
    split_store(g_combh, g_combl, base + 1024 + c2 + 1, cr);
    split_store(g_combh, g_combl, base + 2048 + c2, b.x);
    split_store(g_combh, g_combl, base + 2048 + c2 + 1, b.y);
    split_store(g_combh, g_combl, base + 3072 + c2, sp);
    split_store(g_combh, g_combl, base + 3072 + c2 + 1, cp);
}

// ---------------------------------------------------------------------------
// HMMA GEMM: C[M,N] = act(A[M,Kd] @ Bt[N,Kd]^T + bias)
// A,Bt as hi/lo fp16, K contiguous. 3-MMA compensation: AhBh + AhBl + AlBh.
// BM=BN=128, BK=64 (128B rows, SW128 xor swizzle), 8 warps (2x4), warp 64x32,
// 3-stage cp.async pipeline.
// ---------------------------------------------------------------------------
#define BM 128
#define BN 128
#define BKK 64
#define STAGES 3
#define TILE_BYTES 16384            // 128 rows x 128 bytes
#define STAGE_BYTES (4 * TILE_BYTES) // Ah | Al | Bh | Bl
#define DYN_SMEM (STAGES * STAGE_BYTES)

__device__ __forceinline__ uint32_t sw_off(int row, int ch) {
    return (uint32_t)(row * 128 + ((ch ^ (row & 7)) << 4));
}

__device__ __forceinline__ void load_tile(uint32_t sbase, const __half* g,
                                          int ldk, int tid) {
    // 128 rows x 8 chunks of 16B = 1024 chunks; 256 threads -> 4 each
#pragma unroll
    for (int i = 0; i < 4; i++) {
        int id = tid + i * 256;
        int row = id >> 3, ch = id & 7;
        cp_async16(sbase + sw_off(row, ch), g + (size_t)row * ldk + ch * 8);
    }
}

template <bool RELU, bool SPLIT>
__global__ __launch_bounds__(256, 1) void hmma_gemm_kernel(
    const __half* __restrict__ Ah, const __half* __restrict__ Al,
    const __half* __restrict__ Bh, const __half* __restrict__ Bl,
    const float* __restrict__ bias,
    float* __restrict__ Cf, __half* __restrict__ Ch, __half* __restrict__ Cl,
    int N, int Kd) {
    extern __shared__ char smem[];
    const uint32_t sbase = smem_u32(smem);

    const int tid = threadIdx.x;
    const int wid = tid >> 5;
    const int lane = tid & 31;
    const int wm = wid >> 2;          // 0..1  (64-row slice)
    const int wn = wid & 3;           // 0..3  (32-col slice)

    const size_t m0 = (size_t)blockIdx.y * BM;
    const size_t n0 = (size_t)blockIdx.x * BN;
    const int NC = Kd / BKK;

    const __half* gAh = Ah + m0 * Kd;
    const __half* gAl = Al + m0 * Kd;
    const __half* gBh = Bh + n0 * Kd;
    const __half* gBl = Bl + n0 * Kd;

    // prologue: prefetch STAGES-1 stages
#pragma unroll
    for (int s = 0; s < STAGES - 1; s++) {
        uint32_t sb = sbase + s * STAGE_BYTES;
        int k0 = s * BKK;
        load_tile(sb + 0 * TILE_BYTES, gAh + k0, Kd, tid);
        load_tile(sb + 1 * TILE_BYTES, gAl + k0, Kd, tid);
        load_tile(sb + 2 * TILE_BYTES, gBh + k0, Kd, tid);
        load_tile(sb + 3 * TILE_BYTES, gBl + k0, Kd, tid);
        CP_COMMIT();
    }

    float acc[4][4][4];
#pragma unroll
    for (int mi = 0; mi < 4; mi++)
#pragma unroll
        for (int ni = 0; ni < 4; ni++)
#pragma unroll
            for (int q = 0; q < 4; q++) acc[mi][ni][q] = 0.0f;

    // ldmatrix lane-addressing (row within tile, chunk base)
    const int a_row = wm * 64 + (lane & 15);           // + mi*16
    const int b_row = wn * 32 + (lane & 15);           // + j*16
    const int kc_lane = lane >> 4;                     // 0/1

    for (int c = 0; c < NC; c++) {
        CP_WAIT(STAGES - 2);
        __syncthreads();

        int pf = c + STAGES - 1;
        if (pf < NC) {
            uint32_t sb = sbase + (pf % STAGES) * STAGE_BYTES;
            int k0 = pf * BKK;
            load_tile(sb + 0 * TILE_BYTES, gAh + k0, Kd, tid);
            load_tile(sb + 1 * TILE_BYTES, gAl + k0, Kd, tid);
            load_tile(sb + 2 * TILE_BYTES, gBh + k0, Kd, tid);
            load_tile(sb + 3 * TILE_BYTES, gBl + k0, Kd, tid);
        }
        CP_COMMIT();

        uint32_t sAh = sbase + (c % STAGES) * STAGE_BYTES;
        uint32_t sAl = sAh + TILE_BYTES;
        uint32_t sBh = sAl + TILE_BYTES;
        uint32_t sBl = sBh + TILE_BYTES;

#pragma unroll
        for (int ks = 0; ks < 4; ks++) {
            int kc = ks * 2 + kc_lane;
            uint32_t a_h[4][4], a_l[4][4];
#pragma unroll
            for (int mi = 0; mi < 4; mi++) {
                uint32_t off = sw_off(a_row + mi * 16, kc);
                ldsm_x4(a_h[mi], sAh + off);
                ldsm_x4(a_l[mi], sAl + off);
            }
            uint32_t b_h[2][4], b_l[2][4];
#pragma unroll
            for (int j = 0; j < 2; j++) {
                uint32_t off = sw_off(b_row + j * 16, kc);
                ldsm_x4(b_h[j], sBh + off);
                ldsm_x4(b_l[j], sBl + off);
            }
#pragma unroll
            for (int mi = 0; mi < 4; mi++) {
#pragma unroll
                for (int ni = 0; ni < 4; ni++) {
                    int j = ni >> 1, s = ni & 1;
                    mma16816(acc[mi][ni], a_h[mi], b_h[j][s], b_h[j][s + 2]);
                    mma16816(acc[mi][ni], a_h[mi], b_l[j][s], b_l[j][s + 2]);
                    mma16816(acc[mi][ni], a_l[mi], b_h[j][s], b_h[j][s + 2]);
                }
            }
        }
        __syncthreads();
    }

    // Epilogue
    const int tm = lane >> 2;
    const int tn = lane & 3;
#pragma unroll
    for (int mi = 0; mi < 4; mi++) {
#pragma unroll
        for (int h = 0; h < 2; h++) {
            size_t row = m0 + wm * 64 + mi * 16 + h * 8 + tm;
#pragma unroll
            for (int ni = 0; ni < 4; ni++) {
                size_t col = n0 + wn * 32 + ni * 8 + tn * 2;
                float2 bv = *(const float2*)(bias + col);
                float v0 = acc[mi][ni][h * 2 + 0] + bv.x;
                float v1 = acc[mi][ni][h * 2 + 1] + bv.y;
                if (RELU) { v0 = fmaxf(v0, 0.0f); v1 = fmaxf(v1, 0.0f); }
                if (SPLIT) {
                    __half h0 = __float2half_rn(v0);
                    __half h1 = __float2half_rn(v1);
                    __half l0 = __float2half_rn(v0 - __half2float(h0));
                    __half l1 = __float2half_rn(v1 - __half2float(h1));
                    *(__half2*)(Ch + row * N + col) = __half2(h0, h1);
                    *(__half2*)(Cl + row * N + col) = __half2(l0, l1);
                } else {
                    *(float2*)(Cf + row * N + col) = make_float2(v0, v1);
                }
            }
        }
    }
}

// ---------------------------------------------------------------------------
// Launch
// ---------------------------------------------------------------------------
extern "C" void kernel_launch(void* const* d_in, const int* in_sizes, int n_in,
                              void* d_out, int out_size) {
    const float* positions = (const float*)d_in[0];
    const int*   parent    = (const int*)d_in[1];
    const float* W1 = (const float*)d_in[2];
    const float* b1 = (const float*)d_in[3];
    const float* W2 = (const float*)d_in[4];
    const float* b2 = (const float*)d_in[5];
    const float* W3 = (const float*)d_in[6];
    const float* b3 = (const float*)d_in[7];
    const float* W4 = (const float*)d_in[8];
    const float* b4 = (const float*)d_in[9];
    float* out = (float*)d_out;

    __half *dHh, *dHl, *dcombh, *dcombl, *dh3h, *dh3l;
    __half *dW2th, *dW2tl, *dW3th, *dW3tl, *dW4th, *dW4tl;
    float* djk;
    cudaGetSymbolAddress((void**)&dHh, g_Hh);
    cudaGetSymbolAddress((void**)&dHl, g_Hl);
    cudaGetSymbolAddress((void**)&djk, g_jk);
    cudaGetSymbolAddress((void**)&dcombh, g_combh);
    cudaGetSymbolAddress((void**)&dcombl, g_combl);
    cudaGetSymbolAddress((void**)&dh3h, g_h3h);
    cudaGetSymbolAddress((void**)&dh3l, g_h3l);
    cudaGetSymbolAddress((void**)&dW2th, g_W2th);
    cudaGetSymbolAddress((void**)&dW2tl, g_W2tl);
    cudaGetSymbolAddress((void**)&dW3th, g_W3th);
    cudaGetSymbolAddress((void**)&dW3tl, g_W3tl);
    cudaGetSymbolAddress((void**)&dW4th, g_W4th);
    cudaGetSymbolAddress((void**)&dW4tl, g_W4tl);

    cudaFuncSetAttribute(hmma_gemm_kernel<false, false>,
                         cudaFuncAttributeMaxDynamicSharedMemorySize, DYN_SMEM);
    cudaFuncSetAttribute(hmma_gemm_kernel<true, true>,
                         cudaFuncAttributeMaxDynamicSharedMemorySize, DYN_SMEM);

    // weight transpose+split
    transpose_split_kernel<<<dim3(1024 / 32, 512 / 32), dim3(32, 8)>>>(W2, dW2th, dW2tl, 512, 1024);
    transpose_split_kernel<<<dim3(2048 / 32, 4096 / 32), dim3(32, 8)>>>(W3, dW3th, dW3tl, 4096, 2048);
    transpose_split_kernel<<<dim3(1024 / 32, 2048 / 32), dim3(32, 8)>>>(W4, dW4th, dW4tl, 2048, 1024);

    // Stage 1
    mlp1_kernel<<<(KTOK * 512) / 256, 256>>>(positions, W1, b1);

    // Stage 2: jk = H @ W2 + b2   [K,1024] fp32
    hmma_gemm_kernel<false, false><<<dim3(1024 / BN, KTOK / BM), 256, DYN_SMEM>>>(
        dHh, dHl, dW2th, dW2tl, b2, djk, nullptr, nullptr, 1024, 512);

    // Stage 3: combined hi/lo [K,4096]
    build_combined_kernel<<<(KTOK * 512) / 256, 256>>>(parent);

    // Stage 4: h3 = relu(comb @ W3 + b3) -> hi/lo [K,2048]
    hmma_gemm_kernel<true, true><<<dim3(2048 / BN, KTOK / BM), 256, DYN_SMEM>>>(
        dcombh, dcombl, dW3th, dW3tl, b3, nullptr, dh3h, dh3l, 2048, 4096);

    // Stage 5: out = h3 @ W4 + b4  [K,1024] fp32
    hmma_gemm_kernel<false, false><<<dim3(1024 / BN, KTOK / BM), 256, DYN_SMEM>>>(
        dh3h, dh3l, dW4th, dW4tl, b4, out, nullptr, nullptr, 1024, 2048);
}

// round 4
// speedup vs baseline: 4.5857x; 1.7280x over previous
#include <cuda_runtime.h>
#include <cuda_fp16.h>
#include <math.h>
#include <stdint.h>

#define KTOK 16384

// ---------------------------------------------------------------------------
// Scratch (__device__ globals per allocation rules)
// ---------------------------------------------------------------------------
__device__ __half g_Aph[(size_t)KTOK * 1536];        // [H | gamma] hi
__device__ __half g_Apl[(size_t)KTOK * 1536];        // [H | gamma] lo
__device__ __half g_Bp[(size_t)4096 * 1536];         // B' (hi only)
__device__ __half g_W2h[512 * 1024];                 // W2 hi
__device__ __half g_W3th[(size_t)2048 * 4096];       // W3^T hi
__device__ __half g_W3tl[(size_t)2048 * 4096];       // W3^T lo
__device__ __half g_W4th[(size_t)1024 * 2048];       // W4^T hi
__device__ __half g_W4tl[(size_t)1024 * 2048];       // (unused lo)
__device__ float  g_bias3[2048];                     // b3 + b2·W3a + b2·W3c
__device__ float  g_UV[(size_t)KTOK * 4096];
__device__ __half g_h3h[(size_t)KTOK * 2048];
__device__ __half g_h3l[(size_t)KTOK * 2048];

// ---------------------------------------------------------------------------
// PTX primitives (sm_80-era, compile under compute_103)
// ---------------------------------------------------------------------------
__device__ __forceinline__ uint32_t smem_u32(const void* p) {
    uint32_t a;
    asm("{ .reg .u64 t; cvta.to.shared.u64 t, %1; cvt.u32.u64 %0, t; }" : "=r"(a) : "l"(p));
    return a;
}
__device__ __forceinline__ void cp_async16(uint32_t dst, const void* src) {
    asm volatile("cp.async.cg.shared.global [%0], [%1], 16;" :: "r"(dst), "l"(src));
}
#define CP_COMMIT() asm volatile("cp.async.commit_group;" ::: "memory")
#define CP_WAIT(n)  asm volatile("cp.async.wait_group %0;" :: "n"(n) : "memory")

__device__ __forceinline__ void ldsm_x4(uint32_t* r, uint32_t addr) {
    asm volatile("ldmatrix.sync.aligned.m8n8.x4.shared.b16 {%0,%1,%2,%3}, [%4];"
                 : "=r"(r[0]), "=r"(r[1]), "=r"(r[2]), "=r"(r[3]) : "r"(addr));
}
__device__ __forceinline__ void mma16816(float* d, const uint32_t* a,
                                         uint32_t b0, uint32_t b1) {
    asm volatile("mma.sync.aligned.m16n8k16.row.col.f32.f16.f16.f32 "
                 "{%0,%1,%2,%3}, {%4,%5,%6,%7}, {%8,%9}, {%0,%1,%2,%3};"
                 : "+f"(d[0]), "+f"(d[1]), "+f"(d[2]), "+f"(d[3])
                 : "r"(a[0]), "r"(a[1]), "r"(a[2]), "r"(a[3]), "r"(b0), "r"(b1));
}
__device__ __forceinline__ void split_store(__half* hi, __half* lo, size_t idx, float v) {
    __half h = __float2half_rn(v);
    hi[idx] = h;
    lo[idx] = __float2half_rn(v - __half2float(h));
}

// ---------------------------------------------------------------------------
// Elementwise / prep kernels
// ---------------------------------------------------------------------------
// H = relu(pos @ W1 + b1) -> A' cols [0,512)
__global__ void mlp1_kernel(const float* __restrict__ pos,
                            const float* __restrict__ W1,
                            const float* __restrict__ b1) {
    int idx = blockIdx.x * blockDim.x + threadIdx.x;   // K*512
    int r = idx >> 9;
    int j = idx & 511;
    float a = b1[j];
    a = fmaf(pos[r * 3 + 0], W1[j], a);
    a = fmaf(pos[r * 3 + 1], W1[512 + j], a);
    a = fmaf(pos[r * 3 + 2], W1[1024 + j], a);
    a = fmaxf(a, 0.0f);
    split_store(g_Aph, g_Apl, (size_t)r * 1536 + j, a);
}

// gamma(k) -> A' cols [512,1536)
__global__ void gamma_kernel() {
    int idx = blockIdx.x * blockDim.x + threadIdx.x;   // K*512
    int k = idx >> 9;
    int i = idx & 511;
    float denom = powf(10000.0f, (float)i * (1.0f / 512.0f));
    float s, c;
    sincosf((float)k / denom, &s, &c);
    size_t base = (size_t)k * 1536 + 512 + 2 * i;
    split_store(g_Aph, g_Apl, base, s);
    split_store(g_Aph, g_Apl, base + 1, c);
}

// transpose+split: in fp32 [R,C] -> out hi/lo fp16 [C,R]
__global__ void transpose_split_kernel(const float* __restrict__ in,
                                       __half* __restrict__ oh,
                                       __half* __restrict__ ol,
                                       int R, int C) {
    __shared__ float tile[32][33];
    int c = blockIdx.x * 32 + threadIdx.x;
    int r0 = blockIdx.y * 32;
#pragma unroll
    for (int k = 0; k < 32; k += 8)
        tile[threadIdx.y + k][threadIdx.x] = in[(size_t)(r0 + threadIdx.y + k) * C + c];
    __syncthreads();
    int orow0 = blockIdx.x * 32;
    int ocol = r0 + threadIdx.x;
#pragma unroll
    for (int k = 0; k < 32; k += 8) {
        float v = tile[threadIdx.x][threadIdx.y + k];
        split_store(oh, ol, (size_t)(orow0 + threadIdx.y + k) * R + ocol, v);
    }
}

__global__ void split_w2_kernel(const float* __restrict__ W2) {
    int idx = blockIdx.x * blockDim.x + threadIdx.x;   // 512*1024
    g_W2h[idx] = __float2half_rn(W2[idx]);
}

// B' cols [512,1536): gamma weights from W3^T
__global__ void copy_gw_kernel() {
    int idx = blockIdx.x * blockDim.x + threadIdx.x;   // 4096*128 (8 halves each)
    int n = idx >> 7;
    int c = idx & 127;
    size_t src = (n < 2048) ? ((size_t)n * 4096 + 1024 + c * 8)
                            : ((size_t)(n - 2048) * 4096 + 3072 + c * 8);
    *(uint4*)(g_Bp + (size_t)n * 1536 + 512 + c * 8) = *(const uint4*)(g_W3th + src);
}

// bias3[m] = b3[m] + sum_j b2[j]*(W3[j,m] + W3[2048+j,m]); warp per m
__global__ void bias3_kernel(const float* __restrict__ W3,
                             const float* __restrict__ b2,
                             const float* __restrict__ b3) {
    int warp = (blockIdx.x * blockDim.x + threadIdx.x) >> 5;   // 2048 warps
    int lane = threadIdx.x & 31;
    float s = 0.0f;
    for (int j = lane; j < 1024; j += 32)
        s += b2[j] * (W3[(size_t)j * 2048 + warp] + W3[(size_t)(2048 + j) * 2048 + warp]);
#pragma unroll
    for (int o = 16; o > 0; o >>= 1) s += __shfl_xor_sync(0xFFFFFFFF, s, o);
    if (lane == 0) g_bias3[warp] = b3[warp] + s;
}

// h3 = relu(UV[k,0:2048] + UV[par[k],2048:4096] + bias3) -> hi/lo split
__global__ void combine_kernel(const int* __restrict__ parent) {
    int idx = blockIdx.x * blockDim.x + threadIdx.x;   // K*512
    int k = idx >> 9;
    int m = (idx & 511) * 4;
    int p = parent[k];
    float4 a = *(const float4*)(g_UV + (size_t)k * 4096 + m);
    float4 b = *(const float4*)(g_UV + (size_t)p * 4096 + 2048 + m);
    float4 bb = *(const float4*)(g_bias3 + m);
    float v[4] = {fmaxf(a.x + b.x + bb.x, 0.0f), fmaxf(a.y + b.y + bb.y, 0.0f),
                  fmaxf(a.z + b.z + bb.z, 0.0f), fmaxf(a.w + b.w + bb.w, 0.0f)};
    __half hh[4], ll[4];
#pragma unroll
    for (int q = 0; q < 4; q++) {
        hh[q] = __float2half_rn(v[q]);
        ll[q] = __float2half_rn(v[q] - __half2float(hh[q]));
    }
    *(uint2*)(g_h3h + (size_t)k * 2048 + m) = *(uint2*)hh;
    *(uint2*)(g_h3l + (size_t)k * 2048 + m) = *(uint2*)ll;
}

// ---------------------------------------------------------------------------
// HMMA GEMM: C[M,N] = A[M,Kd] @ Bt[N,Kd]^T (+bias), 2-pass: Ah*Bh + Al*Bh
// BM=BN=128, BK=64 (128B rows, xor swizzle), 8 warps (2x4), 4-stage cp.async.
// OUT: 0 = fp32, 2 = fp16 hi-only.
// ---------------------------------------------------------------------------
#define BM 128
#define BN 128
#define BKK 64
#define STAGES 4
#define TILE_BYTES 16384
#define STAGE_BYTES (3 * TILE_BYTES)   // Ah | Al | Bh
#define DYN_SMEM (STAGES * STAGE_BYTES)

__device__ __forceinline__ uint32_t sw_off(int row, int ch) {
    return (uint32_t)(row * 128 + ((ch ^ (row & 7)) << 4));
}
__device__ __forceinline__ void load_tile(uint32_t sbase, const __half* g,
                                          int ldk, int tid) {
#pragma unroll
    for (int i = 0; i < 4; i++) {
        int id = tid + i * 256;
        int row = id >> 3, ch = id & 7;
        cp_async16(sbase + sw_off(row, ch), g + (size_t)row * ldk + ch * 8);
    }
}

template <int OUT, bool BIAS>
__global__ __launch_bounds__(256, 1) void hmma_gemm_kernel(
    const __half* __restrict__ Ah, const __half* __restrict__ Al,
    const __half* __restrict__ Bh, const float* __restrict__ bias,
    float* __restrict__ Cf, __half* __restrict__ Ch,
    int Kd, int ldA, int ldB, int ldC) {
    extern __shared__ char smem[];
    const uint32_t sbase = smem_u32(smem);

    const int tid = threadIdx.x;
    const int wid = tid >> 5;
    const int lane = tid & 31;
    const int wm = wid >> 2;
    const int wn = wid & 3;

    const size_t m0 = (size_t)blockIdx.y * BM;
    const size_t n0 = (size_t)blockIdx.x * BN;
    const int NC = Kd / BKK;

    const __half* gAh = Ah + m0 * ldA;
    const __half* gAl = Al + m0 * ldA;
    const __half* gBh = Bh + n0 * ldB;

#pragma unroll
    for (int s = 0; s < STAGES - 1; s++) {
        uint32_t sb = sbase + s * STAGE_BYTES;
        int k0 = s * BKK;
        load_tile(sb + 0 * TILE_BYTES, gAh + k0, ldA, tid);
        load_tile(sb + 1 * TILE_BYTES, gAl + k0, ldA, tid);
        load_tile(sb + 2 * TILE_BYTES, gBh + k0, ldB, tid);
        CP_COMMIT();
    }

    float acc[4][4][4];
#pragma unroll
    for (int mi = 0; mi < 4; mi++)
#pragma unroll
        for (int ni = 0; ni < 4; ni++)
#pragma unroll
            for (int q = 0; q < 4; q++) acc[mi][ni][q] = 0.0f;

    const int a_row = wm * 64 + (lane & 15);
    const int b_row = wn * 32 + (lane & 15);
    const int kc_lane = lane >> 4;

    for (int c = 0; c < NC; c++) {
        CP_WAIT(STAGES - 2);
        __syncthreads();

        int pf = c + STAGES - 1;
        if (pf < NC) {
            uint32_t sb = sbase + (pf % STAGES) * STAGE_BYTES;
            int k0 = pf * BKK;
            load_tile(sb + 0 * TILE_BYTES, gAh + k0, ldA, tid);
            load_tile(sb + 1 * TILE_BYTES, gAl + k0, ldA, tid);
            load_tile(sb + 2 * TILE_BYTES, gBh + k0, ldB, tid);
        }
        CP_COMMIT();

        uint32_t sAh = sbase + (c % STAGES) * STAGE_BYTES;
        uint32_t sAl = sAh + TILE_BYTES;
        uint32_t sBh = sAl + TILE_BYTES;

#pragma unroll
        for (int ks = 0; ks < 4; ks++) {
            int kc = ks * 2 + kc_lane;
            uint32_t a_h[4][4], a_l[4][4];
#pragma unroll
            for (int mi = 0; mi < 4; mi++) {
                uint32_t off = sw_off(a_row + mi * 16, kc);
                ldsm_x4(a_h[mi], sAh + off);
                ldsm_x4(a_l[mi], sAl + off);
            }
            uint32_t b_h[2][4];
#pragma unroll
            for (int j = 0; j < 2; j++)
                ldsm_x4(b_h[j], sBh + sw_off(b_row + j * 16, kc));
#pragma unroll
            for (int mi = 0; mi < 4; mi++) {
#pragma unroll
                for (int ni = 0; ni < 4; ni++) {
                    int j = ni >> 1, s = ni & 1;
                    mma16816(acc[mi][ni], a_h[mi], b_h[j][s], b_h[j][s + 2]);
                    mma16816(acc[mi][ni], a_l[mi], b_h[j][s], b_h[j][s + 2]);
                }
            }
        }
        __syncthreads();
    }

    const int tm = lane >> 2;
    const int tn = lane & 3;
#pragma unroll
    for (int mi = 0; mi < 4; mi++) {
#pragma unroll
        for (int h = 0; h < 2; h++) {
            size_t row = m0 + wm * 64 + mi * 16 + h * 8 + tm;
#pragma unroll
            for (int ni = 0; ni < 4; ni++) {
                size_t col = n0 + wn * 32 + ni * 8 + tn * 2;
                float v0 = acc[mi][ni][h * 2 + 0];
                float v1 = acc[mi][ni][h * 2 + 1];
                if (BIAS) {
                    float2 bv = *(const float2*)(bias + col);
                    v0 += bv.x; v1 += bv.y;
                }
                if (OUT == 0) {
                    *(float2*)(Cf + row * ldC + col) = make_float2(v0, v1);
                } else {
                    *(__half2*)(Ch + row * ldC + col) =
                        __halves2half2(__float2half_rn(v0), __float2half_rn(v1));
                }
            }
        }
    }
}

// ---------------------------------------------------------------------------
// Launch
// ---------------------------------------------------------------------------
extern "C" void kernel_launch(void* const* d_in, const int* in_sizes, int n_in,
                              void* d_out, int out_size) {
    const float* positions = (const float*)d_in[0];
    const int*   parent    = (const int*)d_in[1];
    const float* W1 = (const float*)d_in[2];
    const float* b1 = (const float*)d_in[3];
    const float* W2 = (const float*)d_in[4];
    const float* b2 = (const float*)d_in[5];
    const float* W3 = (const float*)d_in[6];
    const float* b3 = (const float*)d_in[7];
    const float* W4 = (const float*)d_in[8];
    const float* b4 = (const float*)d_in[9];
    float* out = (float*)d_out;

    __half *dAph, *dApl, *dBp, *dW2h, *dW3th, *dW3tl, *dW4th, *dW4tl, *dh3h, *dh3l;
    float *dUV;
    cudaGetSymbolAddress((void**)&dAph, g_Aph);
    cudaGetSymbolAddress((void**)&dApl, g_Apl);
    cudaGetSymbolAddress((void**)&dBp, g_Bp);
    cudaGetSymbolAddress((void**)&dW2h, g_W2h);
    cudaGetSymbolAddress((void**)&dW3th, g_W3th);
    cudaGetSymbolAddress((void**)&dW3tl, g_W3tl);
    cudaGetSymbolAddress((void**)&dW4th, g_W4th);
    cudaGetSymbolAddress((void**)&dW4tl, g_W4tl);
    cudaGetSymbolAddress((void**)&dUV, g_UV);
    cudaGetSymbolAddress((void**)&dh3h, g_h3h);
    cudaGetSymbolAddress((void**)&dh3l, g_h3l);
    float* dbias3;
    cudaGetSymbolAddress((void**)&dbias3, g_bias3);

    cudaFuncSetAttribute(hmma_gemm_kernel<0, false>,
                         cudaFuncAttributeMaxDynamicSharedMemorySize, DYN_SMEM);
    cudaFuncSetAttribute(hmma_gemm_kernel<0, true>,
                         cudaFuncAttributeMaxDynamicSharedMemorySize, DYN_SMEM);
    cudaFuncSetAttribute(hmma_gemm_kernel<2, false>,
                         cudaFuncAttributeMaxDynamicSharedMemorySize, DYN_SMEM);

    // --- weight prep ---
    transpose_split_kernel<<<dim3(2048 / 32, 4096 / 32), dim3(32, 8)>>>(W3, dW3th, dW3tl, 4096, 2048);
    transpose_split_kernel<<<dim3(1024 / 32, 2048 / 32), dim3(32, 8)>>>(W4, dW4th, dW4tl, 2048, 1024);
    split_w2_kernel<<<(512 * 1024) / 256, 256>>>(W2);
    bias3_kernel<<<256, 256>>>(W3, b2, b3);

    // B' cols [0,512): W3slice^T @ W2^T via two prep GEMMs (A-lo kept = W3 lo)
    hmma_gemm_kernel<2, false><<<dim3(512 / BN, 2048 / BM), 256, DYN_SMEM>>>(
        dW3th, dW3tl, dW2h, nullptr, nullptr, dBp, 1024, 4096, 1024, 1536);
    hmma_gemm_kernel<2, false><<<dim3(512 / BN, 2048 / BM), 256, DYN_SMEM>>>(
        dW3th + 2048, dW3tl + 2048, dW2h, nullptr, nullptr, dBp + (size_t)2048 * 1536,
        1024, 4096, 1024, 1536);
    // B' cols [512,1536): gamma weights
    copy_gw_kernel<<<(4096 * 128) / 256, 256>>>();

    // --- activations ---
    mlp1_kernel<<<(KTOK * 512) / 256, 256>>>(positions, W1, b1);
    gamma_kernel<<<(KTOK * 512) / 256, 256>>>();

    // --- main GEMM: UV = A'[K,1536] @ B'[4096,1536]^T ---
    hmma_gemm_kernel<0, false><<<dim3(4096 / BN, KTOK / BM), 256, DYN_SMEM>>>(
        dAph, dApl, dBp, nullptr, dUV, nullptr, 1536, 1536, 1536, 4096);

    // --- combine + gather + relu + split ---
    combine_kernel<<<(KTOK * 512) / 256, 256>>>(parent);

    // --- final GEMM: out = h3[K,2048] @ W4t[1024,2048]^T + b4 ---
    hmma_gemm_kernel<0, true><<<dim3(1024 / BN, KTOK / BM), 256, DYN_SMEM>>>(
        dh3h, dh3l, dW4th, b4, out, nullptr, 2048, 2048, 2048, 1024);
}

// round 6
// speedup vs baseline: 5.1594x; 1.1251x over previous
#include <cuda_runtime.h>
#include <cuda_fp16.h>
#include <math.h>
#include <stdint.h>

#define KTOK 16384

// ---------------------------------------------------------------------------
// Scratch (__device__ globals per allocation rules)
// ---------------------------------------------------------------------------
__device__ __half g_Aph[(size_t)KTOK * 1536];        // [H | gamma] hi
__device__ __half g_Apl[(size_t)KTOK * 1536];        // [H | gamma] lo
__device__ __half g_Bp[(size_t)4096 * 1536];         // B' (hi only)
__device__ __half g_W2h[512 * 1024];                 // W2 hi
__device__ __half g_W3th[(size_t)2048 * 4096];       // W3^T hi
__device__ __half g_W3tl[(size_t)2048 * 4096];       // W3^T lo
__device__ __half g_W4th[(size_t)1024 * 2048];       // W4^T hi
__device__ __half g_W4tl[(size_t)1024 * 2048];       // scratch lo (unused)
__device__ float  g_bias3[2048];
__device__ float  g_UV[(size_t)KTOK * 4096];
__device__ __half g_h3h[(size_t)KTOK * 2048];

// ---------------------------------------------------------------------------
// PTX primitives (sm_80-era; compile under compute_103)
// ---------------------------------------------------------------------------
__device__ __forceinline__ uint32_t smem_u32(const void* p) {
    uint32_t a;
    asm("{ .reg .u64 t; cvta.to.shared.u64 t, %1; cvt.u32.u64 %0, t; }" : "=r"(a) : "l"(p));
    return a;
}
__device__ __forceinline__ void cp_async16(uint32_t dst, const void* src) {
    asm volatile("cp.async.cg.shared.global [%0], [%1], 16;" :: "r"(dst), "l"(src));
}
#define CP_COMMIT() asm volatile("cp.async.commit_group;" ::: "memory")
#define CP_WAIT(n)  asm volatile("cp.async.wait_group %0;" :: "n"(n) : "memory")

__device__ __forceinline__ void ldsm_x4(uint32_t* r, uint32_t addr) {
    asm volatile("ldmatrix.sync.aligned.m8n8.x4.shared.b16 {%0,%1,%2,%3}, [%4];"
                 : "=r"(r[0]), "=r"(r[1]), "=r"(r[2]), "=r"(r[3]) : "r"(addr));
}
__device__ __forceinline__ void mma16816(float* d, const uint32_t* a,
                                         uint32_t b0, uint32_t b1) {
    asm volatile("mma.sync.aligned.m16n8k16.row.col.f32.f16.f16.f32 "
                 "{%0,%1,%2,%3}, {%4,%5,%6,%7}, {%8,%9}, {%0,%1,%2,%3};"
                 : "+f"(d[0]), "+f"(d[1]), "+f"(d[2]), "+f"(d[3])
                 : "r"(a[0]), "r"(a[1]), "r"(a[2]), "r"(a[3]), "r"(b0), "r"(b1));
}
__device__ __forceinline__ void split_store(__half* hi, __half* lo, size_t idx, float v) {
    __half h = __float2half_rn(v);
    hi[idx] = h;
    lo[idx] = __float2half_rn(v - __half2float(h));
}

// ---------------------------------------------------------------------------
// Activations: A'[r, 0:512) = relu(pos@W1+b1); A'[r, 512:1536) = gamma(r)
// Grid: (6, KTOK), block 256. j = bx*256+tid in [0,1536), r = by.
// ---------------------------------------------------------------------------
__global__ void act_kernel(const float* __restrict__ pos,
                           const float* __restrict__ W1,
                           const float* __restrict__ b1) {
    int j = blockIdx.x * blockDim.x + threadIdx.x;   // [0,1536)
    int r = blockIdx.y;
    float v;
    if (j < 512) {
        float a = b1[j];
        a = fmaf(pos[r * 3 + 0], W1[j], a);
        a = fmaf(pos[r * 3 + 1], W1[512 + j], a);
        a = fmaf(pos[r * 3 + 2], W1[1024 + j], a);
        v = fmaxf(a, 0.0f);
    } else {
        int g = j - 512;             // [0,1024)
        int i = g >> 1;              // [0,512)
        // 1/10000^(i/512) = 2^(-i*log2(10000)/512)
        float inv = exp2f(-(float)i * (13.287712379549449f / 512.0f));
        float s, c;
        sincosf((float)r * inv, &s, &c);
        v = (g & 1) ? c : s;
    }
    split_store(g_Aph, g_Apl, (size_t)r * 1536 + j, v);
}

// transpose+split: in fp32 [R,C] -> out hi/lo fp16 [C,R]
__global__ void transpose_split_kernel(const float* __restrict__ in,
                                       __half* __restrict__ oh,
                                       __half* __restrict__ ol,
                                       int R, int C) {
    __shared__ float tile[32][33];
    int c = blockIdx.x * 32 + threadIdx.x;
    int r0 = blockIdx.y * 32;
#pragma unroll
    for (int k = 0; k < 32; k += 8)
        tile[threadIdx.y + k][threadIdx.x] = in[(size_t)(r0 + threadIdx.y + k) * C + c];
    __syncthreads();
    int orow0 = blockIdx.x * 32;
    int ocol = r0 + threadIdx.x;
#pragma unroll
    for (int k = 0; k < 32; k += 8) {
        float v = tile[threadIdx.x][threadIdx.y + k];
        split_store(oh, ol, (size_t)(orow0 + threadIdx.y + k) * R + ocol, v);
    }
}

__global__ void split_w2_kernel(const float* __restrict__ W2) {
    int idx = blockIdx.x * blockDim.x + threadIdx.x;   // 512*1024
    g_W2h[idx] = __float2half_rn(W2[idx]);
}

// B' cols [512,1536): gamma weights from W3^T
__global__ void copy_gw_kernel() {
    int idx = blockIdx.x * blockDim.x + threadIdx.x;   // 4096*128
    int n = idx >> 7;
    int c = idx & 127;
    size_t src = (n < 2048) ? ((size_t)n * 4096 + 1024 + c * 8)
                            : ((size_t)(n - 2048) * 4096 + 3072 + c * 8);
    *(uint4*)(g_Bp + (size_t)n * 1536 + 512 + c * 8) = *(const uint4*)(g_W3th + src);
}

// bias3[m] = b3[m] + sum_j b2[j]*(W3[j,m] + W3[2048+j,m])
__global__ void bias3_kernel(const float* __restrict__ W3,
                             const float* __restrict__ b2,
                             const float* __restrict__ b3) {
    int warp = (blockIdx.x * blockDim.x + threadIdx.x) >> 5;
    int lane = threadIdx.x & 31;
    float s = 0.0f;
    for (int j = lane; j < 1024; j += 32)
        s += b2[j] * (W3[(size_t)j * 2048 + warp] + W3[(size_t)(2048 + j) * 2048 + warp]);
#pragma unroll
    for (int o = 16; o > 0; o >>= 1) s += __shfl_xor_sync(0xFFFFFFFF, s, o);
    if (lane == 0) g_bias3[warp] = b3[warp] + s;
}

// h3 = relu(UV[k,0:2048] + UV[par[k],2048:4096] + bias3) -> fp16 hi only
__global__ void combine_kernel(const int* __restrict__ parent) {
    int idx = blockIdx.x * blockDim.x + threadIdx.x;   // K*512
    int k = idx >> 9;
    int m = (idx & 511) * 4;
    int p = parent[k];
    float4 a = *(const float4*)(g_UV + (size_t)k * 4096 + m);
    float4 b = *(const float4*)(g_UV + (size_t)p * 4096 + 2048 + m);
    float4 bb = *(const float4*)(g_bias3 + m);
    __half hh[4];
    hh[0] = __float2half_rn(fmaxf(a.x + b.x + bb.x, 0.0f));
    hh[1] = __float2half_rn(fmaxf(a.y + b.y + bb.y, 0.0f));
    hh[2] = __float2half_rn(fmaxf(a.z + b.z + bb.z, 0.0f));
    hh[3] = __float2half_rn(fmaxf(a.w + b.w + bb.w, 0.0f));
    *(uint2*)(g_h3h + (size_t)k * 2048 + m) = *(uint2*)hh;
}

// ---------------------------------------------------------------------------
// HMMA GEMM: C[M,N] = A[M,Kd] @ Bt[N,Kd]^T (+bias)
// BM=128, BN=256, BK=64; 8 warps (2x4), warp tile 64x64.
// LO: 2-pass (Ah*Bh + Al*Bh); else single-pass.
// OUT: 0 = fp32, 2 = fp16 hi-only.
// ---------------------------------------------------------------------------
#define BM 128
#define BN 256
#define BKK 64
#define A_TILE 16384
#define B_TILE 32768
#define DYN_SMEM 196608   // both variants use 192KB

__device__ __forceinline__ uint32_t sw_off(int row, int ch) {
    return (uint32_t)(row * 128 + ((ch ^ (row & 7)) << 4));
}
template <int ROWS>
__device__ __forceinline__ void load_tile(uint32_t sbase, const __half* g,
                                          int ldk, int tid) {
#pragma unroll
    for (int i = 0; i < ROWS * 8 / 256; i++) {
        int id = tid + i * 256;
        int row = id >> 3, ch = id & 7;
        cp_async16(sbase + sw_off(row, ch), g + (size_t)row * ldk + ch * 8);
    }
}

template <int OUT, bool BIAS, bool LO>
__global__ __launch_bounds__(256, 1) void hmma_gemm_kernel(
    const __half* __restrict__ Ah, const __half* __restrict__ Al,
    const __half* __restrict__ Bh, const float* __restrict__ bias,
    float* __restrict__ Cf, __half* __restrict__ Ch,
    int Kd, int ldA, int ldB, int ldC) {
    constexpr int STAGES = LO ? 3 : 4;
    constexpr int STAGE_BYTES = LO ? (2 * A_TILE + B_TILE) : (A_TILE + B_TILE);

    extern __shared__ char smem[];
    const uint32_t sbase = smem_u32(smem);

    const int tid = threadIdx.x;
    const int wid = tid >> 5;
    const int lane = tid & 31;
    const int wm = wid >> 2;          // 0..1
    const int wn = wid & 3;           // 0..3

    const size_t m0 = (size_t)blockIdx.y * BM;
    const size_t n0 = (size_t)blockIdx.x * BN;
    const int NC = Kd / BKK;

    const __half* gAh = Ah + m0 * ldA;
    const __half* gAl = LO ? (Al + m0 * ldA) : nullptr;
    const __half* gBh = Bh + n0 * ldB;

#pragma unroll
    for (int s = 0; s < STAGES - 1; s++) {
        uint32_t sb = sbase + s * STAGE_BYTES;
        int k0 = s * BKK;
        load_tile<128>(sb, gAh + k0, ldA, tid);
        if (LO) load_tile<128>(sb + A_TILE, gAl + k0, ldA, tid);
        load_tile<256>(sb + (LO ? 2 : 1) * A_TILE, gBh + k0, ldB, tid);
        CP_COMMIT();
    }

    float acc[4][8][4];
#pragma unroll
    for (int mi = 0; mi < 4; mi++)
#pragma unroll
        for (int ni = 0; ni < 8; ni++)
#pragma unroll
            for (int q = 0; q < 4; q++) acc[mi][ni][q] = 0.0f;

    const int a_row = wm * 64 + (lane & 15);
    const int b_row = wn * 64 + (lane & 15);
    const int kc_lane = lane >> 4;

    for (int c = 0; c < NC; c++) {
        CP_WAIT(STAGES - 2);
        __syncthreads();

        int pf = c + STAGES - 1;
        if (pf < NC) {
            uint32_t sb = sbase + (pf % STAGES) * STAGE_BYTES;
            int k0 = pf * BKK;
            load_tile<128>(sb, gAh + k0, ldA, tid);
            if (LO) load_tile<128>(sb + A_TILE, gAl + k0, ldA, tid);
            load_tile<256>(sb + (LO ? 2 : 1) * A_TILE, gBh + k0, ldB, tid);
        }
        CP_COMMIT();

        uint32_t sA = sbase + (c % STAGES) * STAGE_BYTES;
        uint32_t sAl = sA + A_TILE;
        uint32_t sB = sA + (LO ? 2 : 1) * A_TILE;

#pragma unroll
        for (int ks = 0; ks < 4; ks++) {
            int kc = ks * 2 + kc_lane;
            uint32_t b_h[4][4];
#pragma unroll
            for (int j = 0; j < 4; j++)
                ldsm_x4(b_h[j], sB + sw_off(b_row + j * 16, kc));
#pragma unroll
            for (int mi = 0; mi < 4; mi++) {
                uint32_t a_h[4], a_l[4];
                uint32_t off = sw_off(a_row + mi * 16, kc);
                ldsm_x4(a_h, sA + off);
                if (LO) ldsm_x4(a_l, sAl + off);
#pragma unroll
                for (int ni = 0; ni < 8; ni++) {
                    int j = ni >> 1, s = ni & 1;
                    mma16816(acc[mi][ni], a_h, b_h[j][s], b_h[j][s + 2]);
                    if (LO) mma16816(acc[mi][ni], a_l, b_h[j][s], b_h[j][s + 2]);
                }
            }
        }
        __syncthreads();
    }

    const int tm = lane >> 2;
    const int tn = lane & 3;
#pragma unroll
    for (int mi = 0; mi < 4; mi++) {
#pragma unroll
        for (int h = 0; h < 2; h++) {
            size_t row = m0 + wm * 64 + mi * 16 + h * 8 + tm;
#pragma unroll
            for (int ni = 0; ni < 8; ni++) {
                size_t col = n0 + wn * 64 + ni * 8 + tn * 2;
                float v0 = acc[mi][ni][h * 2 + 0];
                float v1 = acc[mi][ni][h * 2 + 1];
                if (BIAS) {
                    float2 bv = *(const float2*)(bias + col);
                    v0 += bv.x; v1 += bv.y;
                }
                if (OUT == 0) {
                    *(float2*)(Cf + row * ldC + col) = make_float2(v0, v1);
                } else {
                    *(__half2*)(Ch + row * ldC + col) =
                        __halves2half2(__float2half_rn(v0), __float2half_rn(v1));
                }
            }
        }
    }
}

// ---------------------------------------------------------------------------
// Launch
// ---------------------------------------------------------------------------
extern "C" void kernel_launch(void* const* d_in, const int* in_sizes, int n_in,
                              void* d_out, int out_size) {
    const float* positions = (const float*)d_in[0];
    const int*   parent    = (const int*)d_in[1];
    const float* W1 = (const float*)d_in[2];
    const float* b1 = (const float*)d_in[3];
    const float* W2 = (const float*)d_in[4];
    const float* b2 = (const float*)d_in[5];
    const float* W3 = (const float*)d_in[6];
    const float* b3 = (const float*)d_in[7];
    const float* W4 = (const float*)d_in[8];
    const float* b4 = (const float*)d_in[9];
    float* out = (float*)d_out;

    __half *dAph, *dApl, *dBp, *dW2h, *dW3th, *dW3tl, *dW4th, *dW4tl, *dh3h;
    float *dUV;
    cudaGetSymbolAddress((void**)&dAph, g_Aph);
    cudaGetSymbolAddress((void**)&dApl, g_Apl);
    cudaGetSymbolAddress((void**)&dBp, g_Bp);
    cudaGetSymbolAddress((void**)&dW2h, g_W2h);
    cudaGetSymbolAddress((void**)&dW3th, g_W3th);
    cudaGetSymbolAddress((void**)&dW3tl, g_W3tl);
    cudaGetSymbolAddress((void**)&dW4th, g_W4th);
    cudaGetSymbolAddress((void**)&dW4tl, g_W4tl);
    cudaGetSymbolAddress((void**)&dUV, g_UV);
    cudaGetSymbolAddress((void**)&dh3h, g_h3h);

    cudaFuncSetAttribute(hmma_gemm_kernel<0, false, true>,
                         cudaFuncAttributeMaxDynamicSharedMemorySize, DYN_SMEM);
    cudaFuncSetAttribute(hmma_gemm_kernel<0, true, false>,
                         cudaFuncAttributeMaxDynamicSharedMemorySize, DYN_SMEM);
    cudaFuncSetAttribute(hmma_gemm_kernel<2, false, true>,
                         cudaFuncAttributeMaxDynamicSharedMemorySize, DYN_SMEM);

    // --- weight prep ---
    transpose_split_kernel<<<dim3(2048 / 32, 4096 / 32), dim3(32, 8)>>>(W3, dW3th, dW3tl, 4096, 2048);
    transpose_split_kernel<<<dim3(1024 / 32, 2048 / 32), dim3(32, 8)>>>(W4, dW4th, dW4tl, 2048, 1024);
    split_w2_kernel<<<(512 * 1024) / 256, 256>>>(W2);
    bias3_kernel<<<256, 256>>>(W3, b2, b3);

    // B' cols [0,512): (W3 slices)^T @ W2^T, 2-pass on W3 hi/lo
    hmma_gemm_kernel<2, false, true><<<dim3(512 / BN, 2048 / BM), 256, DYN_SMEM>>>(
        dW3th, dW3tl, dW2h, nullptr, nullptr, dBp, 1024, 4096, 1024, 1536);
    hmma_gemm_kernel<2, false, true><<<dim3(512 / BN, 2048 / BM), 256, DYN_SMEM>>>(
        dW3th + 2048, dW3tl + 2048, dW2h, nullptr, nullptr, dBp + (size_t)2048 * 1536,
        1024, 4096, 1024, 1536);
    copy_gw_kernel<<<(4096 * 128) / 256, 256>>>();

    // --- activations: full [K,1536] coverage ---
    act_kernel<<<dim3(1536 / 256, KTOK), 256>>>(positions, W1, b1);

    // --- main GEMM: UV = A'[K,1536] @ B'[4096,1536]^T (2-pass) ---
    hmma_gemm_kernel<0, false, true><<<dim3(4096 / BN, KTOK / BM), 256, DYN_SMEM>>>(
        dAph, dApl, dBp, nullptr, dUV, nullptr, 1536, 1536, 1536, 4096);

    // --- combine + gather + relu ---
    combine_kernel<<<(KTOK * 512) / 256, 256>>>(parent);

    // --- final GEMM: out = h3[K,2048] @ W4t[1024,2048]^T + b4 (1-pass) ---
    hmma_gemm_kernel<0, true, false><<<dim3(1024 / BN, KTOK / BM), 256, DYN_SMEM>>>(
        dh3h, nullptr, dW4th, b4, out, nullptr, 2048, 2048, 2048, 1024);
}

// round 7
// speedup vs baseline: 7.6447x; 1.4817x over previous
#include <cuda_runtime.h>
#include <cuda_fp16.h>
#include <math.h>
#include <stdint.h>

#define KTOK 16384

// ---------------------------------------------------------------------------
// Scratch (__device__ globals per allocation rules)
// ---------------------------------------------------------------------------
__device__ __half g_Aph[(size_t)KTOK * 1536];        // [H | gamma] hi
__device__ __half g_Bp[(size_t)4096 * 1536];         // B' (hi only)
__device__ __half g_W2h[512 * 1024];                 // W2 hi
__device__ __half g_W3th[(size_t)2048 * 4096];       // W3^T hi
__device__ __half g_W3tl[(size_t)2048 * 4096];       // W3^T lo
__device__ __half g_W4th[(size_t)1024 * 2048];       // W4^T hi
__device__ __half g_W4tl[(size_t)1024 * 2048];       // scratch lo (unused)
__device__ float  g_bias3[2048];
__device__ __half g_UV[(size_t)KTOK * 4096];         // fp16 now
__device__ __half g_h3h[(size_t)KTOK * 2048];

// ---------------------------------------------------------------------------
// PTX primitives (sm_80-era; compile under compute_103)
// ---------------------------------------------------------------------------
__device__ __forceinline__ uint32_t smem_u32(const void* p) {
    uint32_t a;
    asm("{ .reg .u64 t; cvta.to.shared.u64 t, %1; cvt.u32.u64 %0, t; }" : "=r"(a) : "l"(p));
    return a;
}
__device__ __forceinline__ void cp_async16(uint32_t dst, const void* src) {
    asm volatile("cp.async.cg.shared.global [%0], [%1], 16;" :: "r"(dst), "l"(src));
}
#define CP_COMMIT() asm volatile("cp.async.commit_group;" ::: "memory")
#define CP_WAIT(n)  asm volatile("cp.async.wait_group %0;" :: "n"(n) : "memory")

__device__ __forceinline__ void ldsm_x4(uint32_t* r, uint32_t addr) {
    asm volatile("ldmatrix.sync.aligned.m8n8.x4.shared.b16 {%0,%1,%2,%3}, [%4];"
                 : "=r"(r[0]), "=r"(r[1]), "=r"(r[2]), "=r"(r[3]) : "r"(addr));
}
__device__ __forceinline__ void mma16816(float* d, const uint32_t* a,
                                         uint32_t b0, uint32_t b1) {
    asm volatile("mma.sync.aligned.m16n8k16.row.col.f32.f16.f16.f32 "
                 "{%0,%1,%2,%3}, {%4,%5,%6,%7}, {%8,%9}, {%0,%1,%2,%3};"
                 : "+f"(d[0]), "+f"(d[1]), "+f"(d[2]), "+f"(d[3])
                 : "r"(a[0]), "r"(a[1]), "r"(a[2]), "r"(a[3]), "r"(b0), "r"(b1));
}
__device__ __forceinline__ void split_store(__half* hi, __half* lo, size_t idx, float v) {
    __half h = __float2half_rn(v);
    hi[idx] = h;
    lo[idx] = __float2half_rn(v - __half2float(h));
}

// ---------------------------------------------------------------------------
// Activations: A'[r, 0:512) = relu(pos@W1+b1); A'[r, 512:1536) = gamma(r)
// Grid: (6, KTOK), block 256. hi-only store.
// ---------------------------------------------------------------------------
__global__ void act_kernel(const float* __restrict__ pos,
                           const float* __restrict__ W1,
                           const float* __restrict__ b1) {
    int j = blockIdx.x * blockDim.x + threadIdx.x;   // [0,1536)
    int r = blockIdx.y;
    float v;
    if (j < 512) {
        float a = b1[j];
        a = fmaf(pos[r * 3 + 0], W1[j], a);
        a = fmaf(pos[r * 3 + 1], W1[512 + j], a);
        a = fmaf(pos[r * 3 + 2], W1[1024 + j], a);
        v = fmaxf(a, 0.0f);
    } else {
        int g = j - 512;             // [0,1024)
        int i = g >> 1;              // [0,512)
        float inv = exp2f(-(float)i * (13.287712379549449f / 512.0f));
        float s, c;
        sincosf((float)r * inv, &s, &c);
        v = (g & 1) ? c : s;
    }
    g_Aph[(size_t)r * 1536 + j] = __float2half_rn(v);
}

// transpose+split: in fp32 [R,C] -> out hi/lo fp16 [C,R]
__global__ void transpose_split_kernel(const float* __restrict__ in,
                                       __half* __restrict__ oh,
                                       __half* __restrict__ ol,
                                       int R, int C) {
    __shared__ float tile[32][33];
    int c = blockIdx.x * 32 + threadIdx.x;
    int r0 = blockIdx.y * 32;
#pragma unroll
    for (int k = 0; k < 32; k += 8)
        tile[threadIdx.y + k][threadIdx.x] = in[(size_t)(r0 + threadIdx.y + k) * C + c];
    __syncthreads();
    int orow0 = blockIdx.x * 32;
    int ocol = r0 + threadIdx.x;
#pragma unroll
    for (int k = 0; k < 32; k += 8) {
        float v = tile[threadIdx.x][threadIdx.y + k];
        split_store(oh, ol, (size_t)(orow0 + threadIdx.y + k) * R + ocol, v);
    }
}

__global__ void split_w2_kernel(const float* __restrict__ W2) {
    int idx = blockIdx.x * blockDim.x + threadIdx.x;   // 512*1024
    g_W2h[idx] = __float2half_rn(W2[idx]);
}

// B' cols [512,1536): gamma weights from W3^T
__global__ void copy_gw_kernel() {
    int idx = blockIdx.x * blockDim.x + threadIdx.x;   // 4096*128
    int n = idx >> 7;
    int c = idx & 127;
    size_t src = (n < 2048) ? ((size_t)n * 4096 + 1024 + c * 8)
                            : ((size_t)(n - 2048) * 4096 + 3072 + c * 8);
    *(uint4*)(g_Bp + (size_t)n * 1536 + 512 + c * 8) = *(const uint4*)(g_W3th + src);
}

// bias3[m] = b3[m] + sum_j b2[j]*(W3[j,m] + W3[2048+j,m])
__global__ void bias3_kernel(const float* __restrict__ W3,
                             const float* __restrict__ b2,
                             const float* __restrict__ b3) {
    int warp = (blockIdx.x * blockDim.x + threadIdx.x) >> 5;
    int lane = threadIdx.x & 31;
    float s = 0.0f;
    for (int j = lane; j < 1024; j += 32)
        s += b2[j] * (W3[(size_t)j * 2048 + warp] + W3[(size_t)(2048 + j) * 2048 + warp]);
#pragma unroll
    for (int o = 16; o > 0; o >>= 1) s += __shfl_xor_sync(0xFFFFFFFF, s, o);
    if (lane == 0) g_bias3[warp] = b3[warp] + s;
}

// h3 = relu(UV[k,0:2048] + UV[par[k],2048:4096] + bias3) -> fp16
__global__ void combine_kernel(const int* __restrict__ parent) {
    int idx = blockIdx.x * blockDim.x + threadIdx.x;   // K*256
    int k = idx >> 8;
    int m = (idx & 255) * 8;
    int p = parent[k];
    __half a[8], b[8], hh[8];
    *(uint4*)a = *(const uint4*)(g_UV + (size_t)k * 4096 + m);
    *(uint4*)b = *(const uint4*)(g_UV + (size_t)p * 4096 + 2048 + m);
#pragma unroll
    for (int q = 0; q < 8; q++) {
        float v = __half2float(a[q]) + __half2float(b[q]) + g_bias3[m + q];
        hh[q] = __float2half_rn(fmaxf(v, 0.0f));
    }
    *(uint4*)(g_h3h + (size_t)k * 2048 + m) = *(uint4*)hh;
}

// ---------------------------------------------------------------------------
// HMMA GEMM: C[M,N] = A[M,Kd] @ Bt[N,Kd]^T (+bias)
// BM=128, BN=256, BK=64; 8 warps (2x4), warp tile 64x64.
// LO: 2-pass (Ah*Bh + Al*Bh); else single-pass.
// OUT: 0 = fp32, 2 = fp16.
// ---------------------------------------------------------------------------
#define BM 128
#define BN 256
#define BKK 64
#define A_TILE 16384
#define B_TILE 32768
#define DYN_SMEM 196608

__device__ __forceinline__ uint32_t sw_off(int row, int ch) {
    return (uint32_t)(row * 128 + ((ch ^ (row & 7)) << 4));
}
template <int ROWS>
__device__ __forceinline__ void load_tile(uint32_t sbase, const __half* g,
                                          int ldk, int tid) {
#pragma unroll
    for (int i = 0; i < ROWS * 8 / 256; i++) {
        int id = tid + i * 256;
        int row = id >> 3, ch = id & 7;
        cp_async16(sbase + sw_off(row, ch), g + (size_t)row * ldk + ch * 8);
    }
}

template <int OUT, bool BIAS, bool LO>
__global__ __launch_bounds__(256, 1) void hmma_gemm_kernel(
    const __half* __restrict__ Ah, const __half* __restrict__ Al,
    const __half* __restrict__ Bh, const float* __restrict__ bias,
    float* __restrict__ Cf, __half* __restrict__ Ch,
    int Kd, int ldA, int ldB, int ldC) {
    constexpr int STAGES = LO ? 3 : 4;
    constexpr int STAGE_BYTES = LO ? (2 * A_TILE + B_TILE) : (A_TILE + B_TILE);

    extern __shared__ char smem[];
    const uint32_t sbase = smem_u32(smem);

    const int tid = threadIdx.x;
    const int wid = tid >> 5;
    const int lane = tid & 31;
    const int wm = wid >> 2;
    const int wn = wid & 3;

    const size_t m0 = (size_t)blockIdx.y * BM;
    const size_t n0 = (size_t)blockIdx.x * BN;
    const int NC = Kd / BKK;

    const __half* gAh = Ah + m0 * ldA;
    const __half* gAl = LO ? (Al + m0 * ldA) : nullptr;
    const __half* gBh = Bh + n0 * ldB;

#pragma unroll
    for (int s = 0; s < STAGES - 1; s++) {
        uint32_t sb = sbase + s * STAGE_BYTES;
        int k0 = s * BKK;
        load_tile<128>(sb, gAh + k0, ldA, tid);
        if (LO) load_tile<128>(sb + A_TILE, gAl + k0, ldA, tid);
        load_tile<256>(sb + (LO ? 2 : 1) * A_TILE, gBh + k0, ldB, tid);
        CP_COMMIT();
    }

    float acc[4][8][4];
#pragma unroll
    for (int mi = 0; mi < 4; mi++)
#pragma unroll
        for (int ni = 0; ni < 8; ni++)
#pragma unroll
            for (int q = 0; q < 4; q++) acc[mi][ni][q] = 0.0f;

    const int a_row = wm * 64 + (lane & 15);
    const int b_row = wn * 64 + (lane & 15);
    const int kc_lane = lane >> 4;

    for (int c = 0; c < NC; c++) {
        CP_WAIT(STAGES - 2);
        __syncthreads();

        int pf = c + STAGES - 1;
        if (pf < NC) {
            uint32_t sb = sbase + (pf % STAGES) * STAGE_BYTES;
            int k0 = pf * BKK;
            load_tile<128>(sb, gAh + k0, ldA, tid);
            if (LO) load_tile<128>(sb + A_TILE, gAl + k0, ldA, tid);
            load_tile<256>(sb + (LO ? 2 : 1) * A_TILE, gBh + k0, ldB, tid);
        }
        CP_COMMIT();

        uint32_t sA = sbase + (c % STAGES) * STAGE_BYTES;
        uint32_t sAl = sA + A_TILE;
        uint32_t sB = sA + (LO ? 2 : 1) * A_TILE;

#pragma unroll
        for (int ks = 0; ks < 4; ks++) {
            int kc = ks * 2 + kc_lane;
            uint32_t b_h[4][4];
#pragma unroll
            for (int j = 0; j < 4; j++)
                ldsm_x4(b_h[j], sB + sw_off(b_row + j * 16, kc));
#pragma unroll
            for (int mi = 0; mi < 4; mi++) {
                uint32_t a_h[4], a_l[4];
                uint32_t off = sw_off(a_row + mi * 16, kc);
                ldsm_x4(a_h, sA + off);
                if (LO) ldsm_x4(a_l, sAl + off);
#pragma unroll
                for (int ni = 0; ni < 8; ni++) {
                    int j = ni >> 1, s = ni & 1;
                    mma16816(acc[mi][ni], a_h, b_h[j][s], b_h[j][s + 2]);
                    if (LO) mma16816(acc[mi][ni], a_l, b_h[j][s], b_h[j][s + 2]);
                }
            }
        }
        __syncthreads();
    }

    const int tm = lane >> 2;
    const int tn = lane & 3;
#pragma unroll
    for (int mi = 0; mi < 4; mi++) {
#pragma unroll
        for (int h = 0; h < 2; h++) {
            size_t row = m0 + wm * 64 + mi * 16 + h * 8 + tm;
#pragma unroll
            for (int ni = 0; ni < 8; ni++) {
                size_t col = n0 + wn * 64 + ni * 8 + tn * 2;
                float v0 = acc[mi][ni][h * 2 + 0];
                float v1 = acc[mi][ni][h * 2 + 1];
                if (BIAS) {
                    float2 bv = *(const float2*)(bias + col);
                    v0 += bv.x; v1 += bv.y;
                }
                if (OUT == 0) {
                    *(float2*)(Cf + row * ldC + col) = make_float2(v0, v1);
                } else {
                    *(__half2*)(Ch + row * ldC + col) =
                        __halves2half2(__float2half_rn(v0), __float2half_rn(v1));
                }
            }
        }
    }
}

// ---------------------------------------------------------------------------
// Launch
// ---------------------------------------------------------------------------
extern "C" void kernel_launch(void* const* d_in, const int* in_sizes, int n_in,
                              void* d_out, int out_size) {
    const float* positions = (const float*)d_in[0];
    const int*   parent    = (const int*)d_in[1];
    const float* W1 = (const float*)d_in[2];
    const float* b1 = (const float*)d_in[3];
    const float* W2 = (const float*)d_in[4];
    const float* b2 = (const float*)d_in[5];
    const float* W3 = (const float*)d_in[6];
    const float* b3 = (const float*)d_in[7];
    const float* W4 = (const float*)d_in[8];
    const float* b4 = (const float*)d_in[9];
    float* out = (float*)d_out;

    __half *dAph, *dBp, *dW2h, *dW3th, *dW3tl, *dW4th, *dW4tl, *dh3h, *dUV;
    cudaGetSymbolAddress((void**)&dAph, g_Aph);
    cudaGetSymbolAddress((void**)&dBp, g_Bp);
    cudaGetSymbolAddress((void**)&dW2h, g_W2h);
    cudaGetSymbolAddress((void**)&dW3th, g_W3th);
    cudaGetSymbolAddress((void**)&dW3tl, g_W3tl);
    cudaGetSymbolAddress((void**)&dW4th, g_W4th);
    cudaGetSymbolAddress((void**)&dW4tl, g_W4tl);
    cudaGetSymbolAddress((void**)&dUV, g_UV);
    cudaGetSymbolAddress((void**)&dh3h, g_h3h);

    cudaFuncSetAttribute(hmma_gemm_kernel<2, false, false>,
                         cudaFuncAttributeMaxDynamicSharedMemorySize, DYN_SMEM);
    cudaFuncSetAttribute(hmma_gemm_kernel<0, true, false>,
                         cudaFuncAttributeMaxDynamicSharedMemorySize, DYN_SMEM);
    cudaFuncSetAttribute(hmma_gemm_kernel<2, false, true>,
                         cudaFuncAttributeMaxDynamicSharedMemorySize, DYN_SMEM);

    // --- weight prep ---
    transpose_split_kernel<<<dim3(2048 / 32, 4096 / 32), dim3(32, 8)>>>(W3, dW3th, dW3tl, 4096, 2048);
    transpose_split_kernel<<<dim3(1024 / 32, 2048 / 32), dim3(32, 8)>>>(W4, dW4th, dW4tl, 2048, 1024);
    split_w2_kernel<<<(512 * 1024) / 256, 256>>>(W2);
    bias3_kernel<<<256, 256>>>(W3, b2, b3);

    // B' cols [0,512): (W3 slices)^T @ W2^T, 2-pass on W3 hi/lo (accuracy)
    hmma_gemm_kernel<2, false, true><<<dim3(512 / BN, 2048 / BM), 256, DYN_SMEM>>>(
        dW3th, dW3tl, dW2h, nullptr, nullptr, dBp, 1024, 4096, 1024, 1536);
    hmma_gemm_kernel<2, false, true><<<dim3(512 / BN, 2048 / BM), 256, DYN_SMEM>>>(
        dW3th + 2048, dW3tl + 2048, dW2h, nullptr, nullptr, dBp + (size_t)2048 * 1536,
        1024, 4096, 1024, 1536);
    copy_gw_kernel<<<(4096 * 128) / 256, 256>>>();

    // --- activations (hi only) ---
    act_kernel<<<dim3(1536 / 256, KTOK), 256>>>(positions, W1, b1);

    // --- main GEMM: UV = A'[K,1536] @ B'[4096,1536]^T (1-pass, fp16 out) ---
    hmma_gemm_kernel<2, false, false><<<dim3(4096 / BN, KTOK / BM), 256, DYN_SMEM>>>(
        dAph, nullptr, dBp, nullptr, nullptr, dUV, 1536, 1536, 1536, 4096);

    // --- combine + gather + relu ---
    combine_kernel<<<(KTOK * 256) / 256, 256>>>(parent);

    // --- final GEMM: out = h3[K,2048] @ W4t[1024,2048]^T + b4 (1-pass) ---
    hmma_gemm_kernel<0, true, false><<<dim3(1024 / BN, KTOK / BM), 256, DYN_SMEM>>>(
        dh3h, nullptr, dW4th, b4, out, nullptr, 2048, 2048, 2048, 1024);
}